// round 1
// baseline (speedup 1.0000x reference)
#include <cuda_runtime.h>
#include <math.h>

#define DD     32
#define DIMN   16
#define NTOT   4096
#define EPSV   1e-5f
#define LAM    0.1f
#define NSWEEP 8
#define WARPS_PER_BLK 8

// ---------------- scratch (device globals: no allocation allowed) -----------
__device__ float2 g_G[DIMN * DIMN];            // sum_d A_d A_d^H
__device__ float2 g_S[DD * DIMN * DIMN];       // A_d + A_d^H
__device__ float2 g_r[DD * DIMN];              // column sums of A_d
__device__ float2 g_r2[DD * DIMN];             // column sums of A_d @ A_d  (= A_d^T r_d)
__device__ double g_acc;

// ---------------- kernel 0: constants from A ------------------------------
__global__ void precompute_kernel(const float* __restrict__ Ar,
                                  const float* __restrict__ Ai) {
    int t = threadIdx.x;            // 256 threads, one per (i,j)
    int i = t >> 4, j = t & 15;
    if (t == 0) g_acc = 0.0;

    float2 g = make_float2(0.f, 0.f);
    for (int d = 0; d < DD; d++) {
        const float* ar = Ar + d * 256;
        const float* ai = Ai + d * 256;
        // S_d = A_d + A_d^H
        float arij = ar[i * 16 + j], aiij = ai[i * 16 + j];
        float arji = ar[j * 16 + i], aiji = ai[j * 16 + i];
        g_S[d * 256 + i * 16 + j] = make_float2(arij + arji, aiij - aiji);
        // G += A_d A_d^H : G[i][j] = sum_k A[i,k] conj(A[j,k])
        for (int k = 0; k < 16; k++) {
            float axr = ar[i * 16 + k], axi = ai[i * 16 + k];
            float bxr = ar[j * 16 + k], bxi = ai[j * 16 + k];
            g.x += axr * bxr + axi * bxi;
            g.y += axi * bxr - axr * bxi;
        }
    }
    g_G[i * 16 + j] = g;

    // r_d[j] = sum_i A_d[i,j]
    for (int e = t; e < DD * 16; e += 256) {
        int d = e >> 4, jj = e & 15;
        float2 s = make_float2(0.f, 0.f);
        for (int ii = 0; ii < 16; ii++) {
            s.x += Ar[d * 256 + ii * 16 + jj];
            s.y += Ai[d * 256 + ii * 16 + jj];
        }
        g_r[e] = s;
    }
    __syncthreads();
    // r2_d[j] = sum_k r_d[k] * A_d[k,j]   (column sums of A_d @ A_d)
    for (int e = t; e < DD * 16; e += 256) {
        int d = e >> 4, jj = e & 15;
        float2 s = make_float2(0.f, 0.f);
        for (int k = 0; k < 16; k++) {
            float2 rk = g_r[d * 16 + k];
            float axr = Ar[d * 256 + k * 16 + jj];
            float axi = Ai[d * 256 + k * 16 + jj];
            s.x += rk.x * axr - rk.y * axi;
            s.y += rk.x * axi + rk.y * axr;
        }
        g_r2[e] = s;
    }
}

// ---------------- kernel 1: build H, Jacobi eigensolver, loss --------------
__global__ void __launch_bounds__(WARPS_PER_BLK * 32)
solve_kernel(const float* __restrict__ X) {
    __shared__ float2 sH[WARPS_PER_BLK][DIMN * 17];
    __shared__ float2 sV[WARPS_PER_BLK][DIMN * 17];
    __shared__ float2 spsi[WARPS_PER_BLK][DIMN];

    const int w    = threadIdx.x >> 5;
    const int lane = threadIdx.x & 31;
    const int n    = blockIdx.x * WARPS_PER_BLK + w;

    float2* H = sH[w];
    float2* V = sV[w];

    // ---- load x_n, ||x||^2 ----
    float x = X[n * DD + lane];
    float sx2 = x * x;
    #pragma unroll
    for (int o = 16; o > 0; o >>= 1) sx2 += __shfl_xor_sync(0xffffffffu, sx2, o);

    // ---- H = 0.5*G - 0.5*sum_d x_d S_d + (eps + 0.5*||x||^2) I ----
    float2 acc[8];
    #pragma unroll
    for (int m = 0; m < 8; m++) {
        float2 g = g_G[m * 32 + lane];
        acc[m] = make_float2(0.5f * g.x, 0.5f * g.y);
    }
    #pragma unroll
    for (int d = 0; d < DD; d++) {
        float xd = __shfl_sync(0xffffffffu, x, d);
        float h  = 0.5f * xd;
        #pragma unroll
        for (int m = 0; m < 8; m++) {
            float2 s = g_S[d * 256 + m * 32 + lane];
            acc[m].x -= h * s.x;
            acc[m].y -= h * s.y;
        }
    }
    #pragma unroll
    for (int m = 0; m < 8; m++) {
        int e = m * 32 + lane;
        int i = e >> 4, j = e & 15;
        if (i == j) acc[m].x += EPSV + 0.5f * sx2;
        H[i * 17 + j] = acc[m];
        V[i * 17 + j] = make_float2((i == j) ? 1.f : 0.f, 0.f);
    }
    __syncwarp();

    // ---- parallel cyclic Jacobi: 8 disjoint pairs per round, 15 rounds ----
    const int jg   = lane >> 2;   // pair group 0..7
    const int rloc = lane & 3;    // worker within group

    for (int sweep = 0; sweep < NSWEEP; sweep++) {
        for (int r = 0; r < 15; r++) {
            int p, q;
            if (jg == 0) { p = 15; q = r % 15; }
            else         { p = (r + jg) % 15; q = (r + 15 - jg) % 15; }

            // rotation params from pre-update H (redundant in 4 lanes/group)
            float  app = H[p * 17 + p].x;
            float  aqq = H[q * 17 + q].x;
            float2 b   = H[p * 17 + q];
            float  ab2 = b.x * b.x + b.y * b.y;
            float c; float2 wv;
            if (ab2 > 1e-28f) {
                float ab  = sqrtf(ab2);
                float tau = (aqq - app) / (2.f * ab);
                float tt  = ((tau >= 0.f) ? 1.f : -1.f) /
                            (fabsf(tau) + sqrtf(tau * tau + 1.f));
                c = rsqrtf(tt * tt + 1.f);
                float s = tt * c;
                float inv = s / ab;
                wv = make_float2(b.x * inv, b.y * inv);
            } else {
                c = 1.f; wv = make_float2(0.f, 0.f);
            }
            __syncwarp();

            // phase A: H <- H*U, V <- V*U  (column updates, disjoint per group)
            #pragma unroll
            for (int ii = 0; ii < 4; ii++) {
                int i = rloc + ii * 4;
                float2 hp = H[i * 17 + p], hq = H[i * 17 + q];
                H[i * 17 + p] = make_float2(c * hp.x - (wv.x * hq.x + wv.y * hq.y),
                                            c * hp.y - (wv.x * hq.y - wv.y * hq.x));
                H[i * 17 + q] = make_float2(wv.x * hp.x - wv.y * hp.y + c * hq.x,
                                            wv.x * hp.y + wv.y * hp.x + c * hq.y);
                float2 vp = V[i * 17 + p], vq = V[i * 17 + q];
                V[i * 17 + p] = make_float2(c * vp.x - (wv.x * vq.x + wv.y * vq.y),
                                            c * vp.y - (wv.x * vq.y - wv.y * vq.x));
                V[i * 17 + q] = make_float2(wv.x * vp.x - wv.y * vp.y + c * vq.x,
                                            wv.x * vp.y + wv.y * vp.x + c * vq.y);
            }
            __syncwarp();

            // phase B: H <- U^H * H  (row updates, disjoint per group)
            #pragma unroll
            for (int ii = 0; ii < 4; ii++) {
                int jj = rloc + ii * 4;
                float2 hp = H[p * 17 + jj], hq = H[q * 17 + jj];
                H[p * 17 + jj] = make_float2(c * hp.x - (wv.x * hq.x - wv.y * hq.y),
                                             c * hp.y - (wv.x * hq.y + wv.y * hq.x));
                H[q * 17 + jj] = make_float2(wv.x * hp.x + wv.y * hp.y + c * hq.x,
                                             wv.x * hp.y - wv.y * hp.x + c * hq.y);
            }
            __syncwarp();
        }
    }

    // ---- argmin eigenvalue, psi = V[:, m] ----
    float dv  = (lane < 16) ? H[lane * 17 + lane].x : 3.4e38f;
    int   idx = lane;
    #pragma unroll
    for (int o = 16; o > 0; o >>= 1) {
        float ov = __shfl_xor_sync(0xffffffffu, dv, o);
        int   oi = __shfl_xor_sync(0xffffffffu, idx, o);
        if (ov < dv || (ov == dv && oi < idx)) { dv = ov; idx = oi; }
    }

    float2 psi = make_float2(0.f, 0.f);
    if (lane < 16) {
        psi = V[lane * 17 + idx];
        spsi[w][lane] = psi;
    }
    __syncwarp();

    // t = sum_k psi_k (phase normalization cancels in the projector)
    float2 tsum = psi;
    #pragma unroll
    for (int o = 16; o > 0; o >>= 1) {
        tsum.x += __shfl_xor_sync(0xffffffffu, tsum.x, o);
        tsum.y += __shfl_xor_sync(0xffffffffu, tsum.y, o);
    }

    // lane == d : u_d = r_d . psi ; v_d = r2_d . psi
    float2 u  = make_float2(0.f, 0.f);
    float2 v2 = make_float2(0.f, 0.f);
    #pragma unroll
    for (int j2 = 0; j2 < 16; j2++) {
        float2 pj = spsi[w][j2];
        float2 rr = g_r[lane * 16 + j2];
        u.x += rr.x * pj.x - rr.y * pj.y;
        u.y += rr.x * pj.y + rr.y * pj.x;
        float2 r2 = g_r2[lane * 16 + j2];
        v2.x += r2.x * pj.x - r2.y * pj.y;
        v2.y += r2.x * pj.y + r2.y * pj.x;
    }
    float pos = u.x  * tsum.x + u.y  * tsum.y;   // Re(u * conj(t))
    float e2  = v2.x * tsum.x + v2.y * tsum.y;
    float dlt = pos - x;
    float contrib = dlt * dlt + LAM * (e2 - pos * pos);

    #pragma unroll
    for (int o = 16; o > 0; o >>= 1)
        contrib += __shfl_xor_sync(0xffffffffu, contrib, o);
    if (lane == 0) atomicAdd(&g_acc, (double)contrib);
}

// ---------------- kernel 2: finalize ----------------------------------------
__global__ void finalize_kernel(float* __restrict__ out) {
    out[0] = (float)(g_acc * (1.0 / (double)NTOT));
}

extern "C" void kernel_launch(void* const* d_in, const int* in_sizes, int n_in,
                              void* d_out, int out_size) {
    const float* Ar = (const float*)d_in[0];
    const float* Ai = (const float*)d_in[1];
    const float* X  = (const float*)d_in[2];
    float* out = (float*)d_out;

    precompute_kernel<<<1, 256>>>(Ar, Ai);
    solve_kernel<<<NTOT / WARPS_PER_BLK, WARPS_PER_BLK * 32>>>(X);
    finalize_kernel<<<1, 1>>>(out);
}

// round 2
// speedup vs baseline: 3.3860x; 3.3860x over previous
#include <cuda_runtime.h>
#include <math.h>

#define DD     32
#define DIMN   16
#define NTOT   4096
#define EPSV   1e-5f
#define LAM    0.1f
#define NSWEEP 8
#define WARPS_PER_BLK 8

// ---------------- scratch (device globals: no allocation allowed) -----------
__device__ float2 g_G[DIMN * DIMN];            // sum_d A_d A_d^H
__device__ float2 g_S[DD * DIMN * DIMN];       // A_d + A_d^H
__device__ float2 g_r[DD * DIMN];              // column sums of A_d
__device__ float2 g_r2[DD * DIMN];             // column sums of A_d @ A_d
__device__ double g_acc;

// ---------------- kernel -1: zero accumulators ------------------------------
__global__ void zero_kernel() {
    int t = threadIdx.x;
    g_G[t] = make_float2(0.f, 0.f);
    if (t == 0) g_acc = 0.0;
}

// ---------------- kernel 0: constants from A (one block per d) --------------
__global__ void precompute_kernel(const float* __restrict__ Ar,
                                  const float* __restrict__ Ai) {
    __shared__ float2 sr[DIMN];
    const int d = blockIdx.x;
    const int t = threadIdx.x;          // 256 threads, one per (i,j)
    const int i = t >> 4, j = t & 15;
    const float* ar = Ar + d * 256;
    const float* ai = Ai + d * 256;

    // S_d = A_d + A_d^H
    float arij = ar[i * 16 + j], aiij = ai[i * 16 + j];
    float arji = ar[j * 16 + i], aiji = ai[j * 16 + i];
    g_S[d * 256 + t] = make_float2(arij + arji, aiij - aiji);

    // partial G: G[i][j] += sum_k A[i,k] conj(A[j,k])
    float gx = 0.f, gy = 0.f;
    #pragma unroll
    for (int k = 0; k < 16; k++) {
        float axr = ar[i * 16 + k], axi = ai[i * 16 + k];
        float bxr = ar[j * 16 + k], bxi = ai[j * 16 + k];
        gx += axr * bxr + axi * bxi;
        gy += axi * bxr - axr * bxi;
    }
    atomicAdd(&g_G[t].x, gx);
    atomicAdd(&g_G[t].y, gy);

    // r_d[j] = sum_i A_d[i,j]
    if (t < 16) {
        float2 s = make_float2(0.f, 0.f);
        #pragma unroll
        for (int ii = 0; ii < 16; ii++) {
            s.x += ar[ii * 16 + t];
            s.y += ai[ii * 16 + t];
        }
        sr[t] = s;
        g_r[d * 16 + t] = s;
    }
    __syncthreads();
    // r2_d[j] = sum_k r_d[k] * A_d[k,j]
    if (t < 16) {
        float2 s = make_float2(0.f, 0.f);
        #pragma unroll
        for (int k = 0; k < 16; k++) {
            float2 rk = sr[k];
            float axr = ar[k * 16 + t], axi = ai[k * 16 + t];
            s.x += rk.x * axr - rk.y * axi;
            s.y += rk.x * axi + rk.y * axr;
        }
        g_r2[d * 16 + t] = s;
    }
}

// ---------------- kernel 1: build H, one-sided Jacobi in registers ----------
__global__ void __launch_bounds__(WARPS_PER_BLK * 32)
solve_kernel(const float* __restrict__ X) {
    __shared__ float2 sH[WARPS_PER_BLK][DIMN * 17];   // build/transpose buffer
    __shared__ float2 spsi[WARPS_PER_BLK][DIMN];

    const int w    = threadIdx.x >> 5;
    const int lane = threadIdx.x & 31;
    const int n    = blockIdx.x * WARPS_PER_BLK + w;
    const unsigned FULL = 0xffffffffu;

    float2* H = sH[w];

    // ---- load x_n, ||x||^2 ----
    float x = X[n * DD + lane];
    float sx2 = x * x;
    #pragma unroll
    for (int o = 16; o > 0; o >>= 1) sx2 += __shfl_xor_sync(FULL, sx2, o);

    // ---- H = 0.5*G - 0.5*sum_d x_d S_d + (eps + 0.5*||x||^2) I ----
    {
        float2 acc[8];
        #pragma unroll
        for (int m = 0; m < 8; m++) {
            float2 g = g_G[m * 32 + lane];
            acc[m] = make_float2(0.5f * g.x, 0.5f * g.y);
        }
        #pragma unroll
        for (int d = 0; d < DD; d++) {
            float h = 0.5f * __shfl_sync(FULL, x, d);
            #pragma unroll
            for (int m = 0; m < 8; m++) {
                float2 s = g_S[d * 256 + m * 32 + lane];
                acc[m].x -= h * s.x;
                acc[m].y -= h * s.y;
            }
        }
        #pragma unroll
        for (int m = 0; m < 8; m++) {
            int e = m * 32 + lane;
            int i = e >> 4, j = e & 15;
            if (i == j) acc[m].x += EPSV + 0.5f * sx2;
            H[i * 17 + j] = acc[m];
        }
    }
    __syncwarp();

    // ---- register layout: group g = lane>>2 holds columns (2g, 2g+1);
    //      lane rl = lane&3 holds rows {4r+rl} ----
    const int g  = lane >> 2;
    const int rl = lane & 3;

    float2 T[4], B[4];
    #pragma unroll
    for (int r = 0; r < 4; r++) {
        T[r] = H[(r * 4 + rl) * 17 + 2 * g];
        B[r] = H[(r * 4 + rl) * 17 + 2 * g + 1];
    }

    // ---- one-sided Jacobi: 15 rounds/sweep (round-robin), registers only ----
    for (int it = 0; it < NSWEEP * 15; it++) {
        // Gram of the pair this group holds
        float a = 0.f, dq = 0.f, bx = 0.f, by = 0.f;
        #pragma unroll
        for (int r = 0; r < 4; r++) {
            a  += T[r].x * T[r].x + T[r].y * T[r].y;
            dq += B[r].x * B[r].x + B[r].y * B[r].y;
            bx += T[r].x * B[r].x + T[r].y * B[r].y;   // conj(T).B
            by += T[r].x * B[r].y - T[r].y * B[r].x;
        }
        #pragma unroll
        for (int o = 1; o <= 2; o <<= 1) {
            a  += __shfl_xor_sync(FULL, a,  o);
            dq += __shfl_xor_sync(FULL, dq, o);
            bx += __shfl_xor_sync(FULL, bx, o);
            by += __shfl_xor_sync(FULL, by, o);
        }

        // rotation (same formulas as validated two-sided version)
        float ab2 = bx * bx + by * by;
        float c = 1.f, wx = 0.f, wy = 0.f;
        if (ab2 > 1e-28f) {
            float ab  = sqrtf(ab2);
            float tau = (dq - a) / (2.f * ab);
            float tt  = ((tau >= 0.f) ? 1.f : -1.f) /
                        (fabsf(tau) + sqrtf(tau * tau + 1.f));
            c = rsqrtf(tt * tt + 1.f);
            float s   = tt * c;
            float inv = s / ab;
            wx = bx * inv; wy = by * inv;
        }

        // column update: T' = c*T - conj(w)*B ; B' = w*T + c*B
        #pragma unroll
        for (int r = 0; r < 4; r++) {
            float tx = T[r].x, ty = T[r].y;
            float bxr = B[r].x, byr = B[r].y;
            T[r].x = c * tx - (wx * bxr + wy * byr);
            T[r].y = c * ty - (wx * byr - wy * bxr);
            B[r].x = (wx * tx - wy * ty) + c * bxr;
            B[r].y = (wx * ty + wy * tx) + c * byr;
        }

        // round-robin permutation (circle method), top[0] fixed:
        //   newT[g>=2] = T[g-1]; newT[1] = B[0]; newB[g<=6] = B[g+1]; newB[7] = T[7]
        #pragma unroll
        for (int r = 0; r < 4; r++) {
            float upx = __shfl_sync(FULL, T[r].x, lane - 4);
            float upy = __shfl_sync(FULL, T[r].y, lane - 4);
            float f0x = __shfl_sync(FULL, B[r].x, rl);
            float f0y = __shfl_sync(FULL, B[r].y, rl);
            float dnx = __shfl_sync(FULL, B[r].x, lane + 4);
            float dny = __shfl_sync(FULL, B[r].y, lane + 4);
            float2 oldT = T[r];
            if (g >= 2)      T[r] = make_float2(upx, upy);
            else if (g == 1) T[r] = make_float2(f0x, f0y);
            // g==0: keep T
            if (g == 7)      B[r] = oldT;
            else             B[r] = make_float2(dnx, dny);
        }
    }

    // ---- column norms, pick minimum (= min eigenvalue's column) ----
    float nT = 0.f, nB = 0.f;
    #pragma unroll
    for (int r = 0; r < 4; r++) {
        nT += T[r].x * T[r].x + T[r].y * T[r].y;
        nB += B[r].x * B[r].x + B[r].y * B[r].y;
    }
    #pragma unroll
    for (int o = 1; o <= 2; o <<= 1) {
        nT += __shfl_xor_sync(FULL, nT, o);
        nB += __shfl_xor_sync(FULL, nB, o);
    }
    float v; int tag;
    if (nB < nT) { v = nB; tag = 2 * g + 1; } else { v = nT; tag = 2 * g; }
    #pragma unroll
    for (int o = 4; o <= 16; o <<= 1) {
        float ov = __shfl_xor_sync(FULL, v, o);
        int   ot = __shfl_xor_sync(FULL, tag, o);
        if (ov < v || (ov == v && ot < tag)) { v = ov; tag = ot; }
    }

    // psi = winning column / ||column||   (phase normalization cancels)
    float sc = rsqrtf(v);
    if (g == (tag >> 1)) {
        #pragma unroll
        for (int r = 0; r < 4; r++) {
            float2 cv = (tag & 1) ? B[r] : T[r];
            spsi[w][r * 4 + rl] = make_float2(cv.x * sc, cv.y * sc);
        }
    }
    __syncwarp();

    // t = sum_k psi_k
    float2 psi = (lane < 16) ? spsi[w][lane] : make_float2(0.f, 0.f);
    float2 tsum = psi;
    #pragma unroll
    for (int o = 16; o > 0; o >>= 1) {
        tsum.x += __shfl_xor_sync(FULL, tsum.x, o);
        tsum.y += __shfl_xor_sync(FULL, tsum.y, o);
    }

    // lane == d : u_d = r_d . psi ; v_d = r2_d . psi
    float2 u  = make_float2(0.f, 0.f);
    float2 v2 = make_float2(0.f, 0.f);
    #pragma unroll
    for (int j2 = 0; j2 < 16; j2++) {
        float2 pj = spsi[w][j2];
        float2 rr = g_r[lane * 16 + j2];
        u.x += rr.x * pj.x - rr.y * pj.y;
        u.y += rr.x * pj.y + rr.y * pj.x;
        float2 r2 = g_r2[lane * 16 + j2];
        v2.x += r2.x * pj.x - r2.y * pj.y;
        v2.y += r2.x * pj.y + r2.y * pj.x;
    }
    float pos = u.x  * tsum.x + u.y  * tsum.y;   // Re(u * conj(t))
    float e2  = v2.x * tsum.x + v2.y * tsum.y;
    float dlt = pos - x;
    float contrib = dlt * dlt + LAM * (e2 - pos * pos);

    #pragma unroll
    for (int o = 16; o > 0; o >>= 1)
        contrib += __shfl_xor_sync(FULL, contrib, o);
    if (lane == 0) atomicAdd(&g_acc, (double)contrib);
}

// ---------------- kernel 2: finalize ----------------------------------------
__global__ void finalize_kernel(float* __restrict__ out) {
    out[0] = (float)(g_acc * (1.0 / (double)NTOT));
}

extern "C" void kernel_launch(void* const* d_in, const int* in_sizes, int n_in,
                              void* d_out, int out_size) {
    const float* Ar = (const float*)d_in[0];
    const float* Ai = (const float*)d_in[1];
    const float* X  = (const float*)d_in[2];
    float* out = (float*)d_out;

    zero_kernel<<<1, 256>>>();
    precompute_kernel<<<DD, 256>>>(Ar, Ai);
    solve_kernel<<<NTOT / WARPS_PER_BLK, WARPS_PER_BLK * 32>>>(X);
    finalize_kernel<<<1, 1>>>(out);
}

// round 3
// speedup vs baseline: 5.7925x; 1.7107x over previous
#include <cuda_runtime.h>
#include <math.h>

#define DD     32
#define DIMN   16
#define NTOT   4096
#define EPSV   1e-5f
#define LAM    0.1f
#define NSWEEP 6
#define WARPS_PER_BLK 8

// ---------------- scratch (device globals: no allocation allowed) -----------
__device__ float2 g_G[DIMN * DIMN];            // sum_d A_d A_d^H
__device__ float2 g_S[DD * DIMN * DIMN];       // A_d + A_d^H
__device__ float2 g_r[DD * DIMN];              // column sums of A_d
__device__ float2 g_r2[DD * DIMN];             // column sums of A_d @ A_d
__device__ double g_acc;

// ---------------- kernel -1: zero accumulators ------------------------------
__global__ void zero_kernel() {
    int t = threadIdx.x;
    g_G[t] = make_float2(0.f, 0.f);
    if (t == 0) g_acc = 0.0;
}

// ---------------- kernel 0: constants from A (one block per d) --------------
__global__ void precompute_kernel(const float* __restrict__ Ar,
                                  const float* __restrict__ Ai) {
    __shared__ float2 sr[DIMN];
    const int d = blockIdx.x;
    const int t = threadIdx.x;          // 256 threads, one per (i,j)
    const int i = t >> 4, j = t & 15;
    const float* ar = Ar + d * 256;
    const float* ai = Ai + d * 256;

    // S_d = A_d + A_d^H
    float arij = ar[i * 16 + j], aiij = ai[i * 16 + j];
    float arji = ar[j * 16 + i], aiji = ai[j * 16 + i];
    g_S[d * 256 + t] = make_float2(arij + arji, aiij - aiji);

    // partial G: G[i][j] += sum_k A[i,k] conj(A[j,k])
    float gx = 0.f, gy = 0.f;
    #pragma unroll
    for (int k = 0; k < 16; k++) {
        float axr = ar[i * 16 + k], axi = ai[i * 16 + k];
        float bxr = ar[j * 16 + k], bxi = ai[j * 16 + k];
        gx += axr * bxr + axi * bxi;
        gy += axi * bxr - axr * bxi;
    }
    atomicAdd(&g_G[t].x, gx);
    atomicAdd(&g_G[t].y, gy);

    // r_d[j] = sum_i A_d[i,j]
    if (t < 16) {
        float2 s = make_float2(0.f, 0.f);
        #pragma unroll
        for (int ii = 0; ii < 16; ii++) {
            s.x += ar[ii * 16 + t];
            s.y += ai[ii * 16 + t];
        }
        sr[t] = s;
        g_r[d * 16 + t] = s;
    }
    __syncthreads();
    // r2_d[j] = sum_k r_d[k] * A_d[k,j]
    if (t < 16) {
        float2 s = make_float2(0.f, 0.f);
        #pragma unroll
        for (int k = 0; k < 16; k++) {
            float2 rk = sr[k];
            float axr = ar[k * 16 + t], axi = ai[k * 16 + t];
            s.x += rk.x * axr - rk.y * axi;
            s.y += rk.x * axi + rk.y * axr;
        }
        g_r2[d * 16 + t] = s;
    }
}

// ---------------- kernel 1: build H, one-sided Jacobi in registers ----------
__global__ void __launch_bounds__(WARPS_PER_BLK * 32)
solve_kernel(const float* __restrict__ X) {
    __shared__ float2 sH[WARPS_PER_BLK][DIMN * 17];   // build/transpose buffer
    __shared__ float2 spsi[WARPS_PER_BLK][DIMN];

    const int w    = threadIdx.x >> 5;
    const int lane = threadIdx.x & 31;
    const int n    = blockIdx.x * WARPS_PER_BLK + w;
    const unsigned FULL = 0xffffffffu;

    float2* H = sH[w];

    // ---- load x_n, ||x||^2 ----
    float x = X[n * DD + lane];
    float sx2 = x * x;
    #pragma unroll
    for (int o = 16; o > 0; o >>= 1) sx2 += __shfl_xor_sync(FULL, sx2, o);

    // ---- H = 0.5*G - 0.5*sum_d x_d S_d + (eps + 0.5*||x||^2) I ----
    {
        float2 acc[8];
        #pragma unroll
        for (int m = 0; m < 8; m++) {
            float2 g = g_G[m * 32 + lane];
            acc[m] = make_float2(0.5f * g.x, 0.5f * g.y);
        }
        #pragma unroll
        for (int d = 0; d < DD; d++) {
            float h = 0.5f * __shfl_sync(FULL, x, d);
            #pragma unroll
            for (int m = 0; m < 8; m++) {
                float2 s = g_S[d * 256 + m * 32 + lane];
                acc[m].x -= h * s.x;
                acc[m].y -= h * s.y;
            }
        }
        #pragma unroll
        for (int m = 0; m < 8; m++) {
            int e = m * 32 + lane;
            int i = e >> 4, j = e & 15;
            if (i == j) acc[m].x += EPSV + 0.5f * sx2;
            H[i * 17 + j] = acc[m];
        }
    }
    __syncwarp();

    // ---- register layout: group g = lane>>2 holds columns (2g, 2g+1);
    //      lane rl = lane&3 holds rows {4r+rl} ----
    const int g  = lane >> 2;
    const int rl = lane & 3;

    float2 T[4], B[4];
    #pragma unroll
    for (int r = 0; r < 4; r++) {
        T[r] = H[(r * 4 + rl) * 17 + 2 * g];
        B[r] = H[(r * 4 + rl) * 17 + 2 * g + 1];
    }

    // ---- one-sided Jacobi: 15 rounds/sweep (round-robin), registers only ----
    for (int it = 0; it < NSWEEP * 15; it++) {
        // Gram of the pair this group holds; only (|B|^2 - |T|^2) and conj(T).B
        float df = 0.f, bx = 0.f, by = 0.f;
        #pragma unroll
        for (int r = 0; r < 4; r++) {
            df += (B[r].x * B[r].x + B[r].y * B[r].y)
                - (T[r].x * T[r].x + T[r].y * T[r].y);
            bx += T[r].x * B[r].x + T[r].y * B[r].y;   // conj(T).B
            by += T[r].x * B[r].y - T[r].y * B[r].x;
        }
        #pragma unroll
        for (int o = 1; o <= 2; o <<= 1) {
            df += __shfl_xor_sync(FULL, df, o);
            bx += __shfl_xor_sync(FULL, bx, o);
            by += __shfl_xor_sync(FULL, by, o);
        }

        // rotation (same formulas as validated two-sided version)
        float ab2 = bx * bx + by * by;
        float c = 1.f, wx = 0.f, wy = 0.f;
        if (ab2 > 1e-28f) {
            float ab  = sqrtf(ab2);
            float tau = df / (2.f * ab);
            float tt  = ((tau >= 0.f) ? 1.f : -1.f) /
                        (fabsf(tau) + sqrtf(tau * tau + 1.f));
            c = rsqrtf(tt * tt + 1.f);
            float s   = tt * c;
            float inv = s / ab;
            wx = bx * inv; wy = by * inv;
        }

        // column update: T' = c*T - conj(w)*B ; B' = w*T + c*B
        // + round-robin permutation fused (circle method, top[0] fixed):
        //   newT[g>=2] = T[g-1]; newT[1] = B[0]; newB[g<=6] = B[g+1]; newB[7] = T[7]
        #pragma unroll
        for (int r = 0; r < 4; r++) {
            float tx = T[r].x, ty = T[r].y;
            float bxr = B[r].x, byr = B[r].y;
            float ntx = c * tx - (wx * bxr + wy * byr);
            float nty = c * ty - (wx * byr - wy * bxr);
            float nbx = (wx * tx - wy * ty) + c * bxr;
            float nby = (wx * ty + wy * tx) + c * byr;

            // merged shuffle: source lane pre-selects what its downstream
            // neighbor needs (g==0 exports B, others export T)
            float selx = (g == 0) ? nbx : ntx;
            float sely = (g == 0) ? nby : nty;
            float upx = __shfl_sync(FULL, selx, lane - 4);
            float upy = __shfl_sync(FULL, sely, lane - 4);
            float dnx = __shfl_sync(FULL, nbx, lane + 4);
            float dny = __shfl_sync(FULL, nby, lane + 4);

            T[r] = (g == 0) ? make_float2(ntx, nty) : make_float2(upx, upy);
            B[r] = (g == 7) ? make_float2(ntx, nty) : make_float2(dnx, dny);
        }
    }

    // ---- column norms, pick minimum (= min eigenvalue's column) ----
    float nT = 0.f, nB = 0.f;
    #pragma unroll
    for (int r = 0; r < 4; r++) {
        nT += T[r].x * T[r].x + T[r].y * T[r].y;
        nB += B[r].x * B[r].x + B[r].y * B[r].y;
    }
    #pragma unroll
    for (int o = 1; o <= 2; o <<= 1) {
        nT += __shfl_xor_sync(FULL, nT, o);
        nB += __shfl_xor_sync(FULL, nB, o);
    }
    float v; int tag;
    if (nB < nT) { v = nB; tag = 2 * g + 1; } else { v = nT; tag = 2 * g; }
    #pragma unroll
    for (int o = 4; o <= 16; o <<= 1) {
        float ov = __shfl_xor_sync(FULL, v, o);
        int   ot = __shfl_xor_sync(FULL, tag, o);
        if (ov < v || (ov == v && ot < tag)) { v = ov; tag = ot; }
    }

    // psi = winning column / ||column||   (phase normalization cancels)
    float sc = rsqrtf(v);
    if (g == (tag >> 1)) {
        #pragma unroll
        for (int r = 0; r < 4; r++) {
            float2 cv = (tag & 1) ? B[r] : T[r];
            spsi[w][r * 4 + rl] = make_float2(cv.x * sc, cv.y * sc);
        }
    }
    __syncwarp();

    // t = sum_k psi_k
    float2 psi = (lane < 16) ? spsi[w][lane] : make_float2(0.f, 0.f);
    float2 tsum = psi;
    #pragma unroll
    for (int o = 16; o > 0; o >>= 1) {
        tsum.x += __shfl_xor_sync(FULL, tsum.x, o);
        tsum.y += __shfl_xor_sync(FULL, tsum.y, o);
    }

    // lane == d : u_d = r_d . psi ; v_d = r2_d . psi
    float2 u  = make_float2(0.f, 0.f);
    float2 v2 = make_float2(0.f, 0.f);
    #pragma unroll
    for (int j2 = 0; j2 < 16; j2++) {
        float2 pj = spsi[w][j2];
        float2 rr = g_r[lane * 16 + j2];
        u.x += rr.x * pj.x - rr.y * pj.y;
        u.y += rr.x * pj.y + rr.y * pj.x;
        float2 r2 = g_r2[lane * 16 + j2];
        v2.x += r2.x * pj.x - r2.y * pj.y;
        v2.y += r2.x * pj.y + r2.y * pj.x;
    }
    float pos = u.x  * tsum.x + u.y  * tsum.y;   // Re(u * conj(t))
    float e2  = v2.x * tsum.x + v2.y * tsum.y;
    float dlt = pos - x;
    float contrib = dlt * dlt + LAM * (e2 - pos * pos);

    #pragma unroll
    for (int o = 16; o > 0; o >>= 1)
        contrib += __shfl_xor_sync(FULL, contrib, o);
    if (lane == 0) atomicAdd(&g_acc, (double)contrib);
}

// ---------------- kernel 2: finalize ----------------------------------------
__global__ void finalize_kernel(float* __restrict__ out) {
    out[0] = (float)(g_acc * (1.0 / (double)NTOT));
}

extern "C" void kernel_launch(void* const* d_in, const int* in_sizes, int n_in,
                              void* d_out, int out_size) {
    const float* Ar = (const float*)d_in[0];
    const float* Ai = (const float*)d_in[1];
    const float* X  = (const float*)d_in[2];
    float* out = (float*)d_out;

    zero_kernel<<<1, 256>>>();
    precompute_kernel<<<DD, 256>>>(Ar, Ai);
    solve_kernel<<<NTOT / WARPS_PER_BLK, WARPS_PER_BLK * 32>>>(X);
    finalize_kernel<<<1, 1>>>(out);
}